// round 1
// baseline (speedup 1.0000x reference)
#include <cuda_runtime.h>
#include <cstddef>

#define NPOS 8192
#define NNEG 4096
#define DIM 64
#define MROWS 24576          // NPOS + 4*NNEG
#define XROWS 12288
#define SIMCOLS 24576
#define LRUC 1

typedef unsigned long long ull;

// ---------------- device scratch (no allocs allowed) ----------------
__device__ float g_get[NPOS * DIM];
__device__ float g_counts[NPOS];
__device__ float g_vis[NPOS];
__device__ int   g_yidx[NPOS];

// ---------------- f32x2 helpers ----------------
__device__ __forceinline__ ull pk2(float lo, float hi) {
    ull r; asm("mov.b64 %0,{%1,%2};" : "=l"(r) : "f"(lo), "f"(hi)); return r;
}
__device__ __forceinline__ void upk2(ull v, float& lo, float& hi) {
    asm("mov.b64 {%0,%1},%2;" : "=f"(lo), "=f"(hi) : "l"(v));
}
__device__ __forceinline__ ull ffma2(ull a, ull b, ull c) {
    ull d; asm("fma.rn.f32x2 %0,%1,%2,%3;" : "=l"(d) : "l"(a), "l"(b), "l"(c)); return d;
}

// ---------------- zero scratch ----------------
__global__ void zero_kernel() {
    const int n = NPOS * DIM + NPOS + NPOS;
    for (int i = blockIdx.x * blockDim.x + threadIdx.x; i < n; i += gridDim.x * blockDim.x) {
        if (i < NPOS * DIM)             g_get[i] = 0.0f;
        else if (i < NPOS * DIM + NPOS) g_counts[i - NPOS * DIM] = 0.0f;
        else                            g_vis[i - NPOS * DIM - NPOS] = 0.0f;
    }
}

// ---------------- visibility scatter ----------------
__global__ void vis_kernel(const int* __restrict__ visible) {
    int i = blockIdx.x * blockDim.x + threadIdx.x;
    if (i < NPOS / 2) g_vis[visible[i]] = 1.0f;
}

// ---------------- fp32 GEMM: C[8192,24576] = A[8192,64] * B[24576,64]^T ----------------
// 128x128 tile, K=64 resident in smem (K-major, XOR-swizzled), 8x8 micro-tile,
// f32x2 packed accumulation (row pairs).
__global__ void __launch_bounds__(256, 2)
gemm_kernel(const float* __restrict__ A, const float* __restrict__ B, float* __restrict__ C) {
    extern __shared__ float smbuf[];
    float* As = smbuf;             // [64][128] swizzled: As[k][m ^ sw(k)]
    float* Bs = smbuf + 64 * 128;  // [64][128]

    const int tid = threadIdx.x;
    const int m0 = blockIdx.y * 128;
    const int n0 = blockIdx.x * 128;

    // ---- load tiles (gmem row-major -> smem K-major transpose + swizzle) ----
    {
        const float4* A4 = (const float4*)(A + (size_t)m0 * DIM);
        const float4* B4 = (const float4*)(B + (size_t)n0 * DIM);
#pragma unroll
        for (int i = 0; i < 8; i++) {
            int f4 = tid + i * 256;       // 0..2047 ; row = f4/16, k0 = (f4%16)*4
            int r  = f4 >> 4;
            int k0 = (f4 & 15) << 2;
            float4 va = A4[f4];
            float4 vb = B4[f4];
#pragma unroll
            for (int j = 0; j < 4; j++) {
                int k  = k0 + j;
                int sw = ((k >> 2) & 7) << 2;
                As[k * 128 + (r ^ sw)] = ((float*)&va)[j];
                Bs[k * 128 + (r ^ sw)] = ((float*)&vb)[j];
            }
        }
    }
    __syncthreads();

    const int ty = tid >> 4, tx = tid & 15;
    const int ra = ty * 8;   // 8 contiguous rows
    const int cb = tx * 8;   // 8 contiguous cols

    ull acc[4][8];
#pragma unroll
    for (int i = 0; i < 4; i++)
#pragma unroll
        for (int j = 0; j < 8; j++) acc[i][j] = 0ull;

#pragma unroll 8
    for (int k = 0; k < 64; k++) {
        int sw = ((k >> 2) & 7) << 2;
        const float* ak = As + k * 128;
        const float* bk = Bs + k * 128;
        float4 a0 = *(const float4*)(ak + ((ra)     ^ sw));
        float4 a1 = *(const float4*)(ak + ((ra + 4) ^ sw));
        float4 b0 = *(const float4*)(bk + ((cb)     ^ sw));
        float4 b1 = *(const float4*)(bk + ((cb + 4) ^ sw));
        ull ap[4] = { pk2(a0.x, a0.y), pk2(a0.z, a0.w), pk2(a1.x, a1.y), pk2(a1.z, a1.w) };
        float bv[8] = { b0.x, b0.y, b0.z, b0.w, b1.x, b1.y, b1.z, b1.w };
#pragma unroll
        for (int j = 0; j < 8; j++) {
            ull bd = pk2(bv[j], bv[j]);
#pragma unroll
            for (int i2 = 0; i2 < 4; i2++) acc[i2][j] = ffma2(ap[i2], bd, acc[i2][j]);
        }
    }

    // ---- epilogue: unpack + coalesced float4 stores ----
#pragma unroll
    for (int i2 = 0; i2 < 4; i2++) {
        float lo[8], hi[8];
#pragma unroll
        for (int j = 0; j < 8; j++) upk2(acc[i2][j], lo[j], hi[j]);
        size_t base0 = (size_t)(m0 + ra + 2 * i2) * SIMCOLS + n0 + cb;
        size_t base1 = base0 + SIMCOLS;
        *(float4*)(C + base0)     = make_float4(lo[0], lo[1], lo[2], lo[3]);
        *(float4*)(C + base0 + 4) = make_float4(lo[4], lo[5], lo[6], lo[7]);
        *(float4*)(C + base1)     = make_float4(hi[0], hi[1], hi[2], hi[3]);
        *(float4*)(C + base1 + 4) = make_float4(hi[4], hi[5], hi[6], hi[7]);
    }
}

// ---------------- per-row argmax over scores = sim[:, :NPOS] (+2 at y[i]) ----------------
__global__ void argmax_kernel(const float* __restrict__ sim, const int* __restrict__ y,
                              float* __restrict__ out_y) {
    __shared__ float sv[256];
    __shared__ int   si[256];
    int row = blockIdx.x;
    const float* p = sim + (size_t)row * SIMCOLS;
    int yv = y[row];
    float bv = -3.402823466e38f;
    int   bi = 0;
    for (int c = threadIdx.x; c < NPOS; c += 256) {
        float v = p[c] + (c == yv ? 2.0f : 0.0f);
        if (v > bv) { bv = v; bi = c; }   // strided ascending -> keeps first max per thread
    }
    sv[threadIdx.x] = bv; si[threadIdx.x] = bi;
    __syncthreads();
    for (int s = 128; s > 0; s >>= 1) {
        if (threadIdx.x < s) {
            float v2 = sv[threadIdx.x + s]; int i2 = si[threadIdx.x + s];
            if (v2 > sv[threadIdx.x] || (v2 == sv[threadIdx.x] && i2 < si[threadIdx.x])) {
                sv[threadIdx.x] = v2; si[threadIdx.x] = i2;
            }
        }
        __syncthreads();
    }
    if (threadIdx.x == 0) { g_yidx[row] = si[0]; out_y[row] = (float)si[0]; }
}

// ---------------- segment sums (get, counts) ----------------
__global__ void segsum_kernel(const float* __restrict__ x) {
    int i = blockIdx.x;          // source row
    int t = threadIdx.x;         // 0..63
    int idx = g_yidx[i];
    atomicAdd(&g_get[idx * DIM + t], x[(size_t)i * DIM + t]);
    if (t == 0) atomicAdd(&g_counts[idx], 1.0f);
}

// ---------------- memory update + normalize + slot writes ----------------
__global__ void update_kernel(const float* __restrict__ x, const float* __restrict__ memory,
                              const float* __restrict__ params, float* __restrict__ outm) {
    int r = blockIdx.x;
    int t = threadIdx.x;  // 32 threads, each handles dims t and t+32
    if (r < NPOS) {
        float mom   = params[3];
        float cnt   = g_counts[r];
        float valid = (cnt > 0.1f ? 1.0f : 0.0f) * g_vis[r];
        float msc   = valid * mom + 1.0f - valid;
        float gsc   = (1.0f - mom) * valid;
        float denom = cnt + 1e-8f;
        float v0 = memory[(size_t)r * DIM + t]      * msc + (g_get[r * DIM + t]      / denom) * gsc;
        float v1 = memory[(size_t)r * DIM + t + 32] * msc + (g_get[r * DIM + t + 32] / denom) * gsc;
        float ss = v0 * v0 + v1 * v1;
#pragma unroll
        for (int o = 16; o; o >>= 1) ss += __shfl_xor_sync(0xffffffffu, ss, o);
        float inv = 1.0f / fmaxf(sqrtf(ss), 1e-12f);
        outm[(size_t)r * DIM + t]      = v0 * inv;
        outm[(size_t)r * DIM + t + 32] = v1 * inv;
    } else if (r >= NPOS + LRUC * NNEG && r < NPOS + LRUC * NNEG + NNEG) {
        int xs = NPOS + (r - (NPOS + LRUC * NNEG));
        outm[(size_t)r * DIM + t]      = x[(size_t)xs * DIM + t];
        outm[(size_t)r * DIM + t + 32] = x[(size_t)xs * DIM + t + 32];
    } else {
        outm[(size_t)r * DIM + t]      = memory[(size_t)r * DIM + t];
        outm[(size_t)r * DIM + t + 32] = memory[(size_t)r * DIM + t + 32];
    }
}

// ---------------- launch ----------------
extern "C" void kernel_launch(void* const* d_in, const int* in_sizes, int n_in,
                              void* d_out, int out_size) {
    const float* x = nullptr;
    const int*   y = nullptr;
    const int*   visible = nullptr;
    const float* memory = nullptr;
    const float* params = nullptr;
    for (int i = 0; i < n_in; i++) {
        switch (in_sizes[i]) {
            case XROWS * DIM: x = (const float*)d_in[i]; break;
            case NPOS:        y = (const int*)d_in[i]; break;
            case NPOS / 2:    visible = (const int*)d_in[i]; break;
            case MROWS * DIM: memory = (const float*)d_in[i]; break;
            case 4:           params = (const float*)d_in[i]; break;
            default: break;   // scalar ints (size 1) ignored; constants are fixed
        }
    }

    float* sim     = (float*)d_out;
    float* out_y   = sim + (size_t)NPOS * SIMCOLS;
    float* out_mem = out_y + NPOS;

    cudaFuncSetAttribute(gemm_kernel, cudaFuncAttributeMaxDynamicSharedMemorySize, 65536);

    zero_kernel<<<512, 256>>>();
    vis_kernel<<<(NPOS / 2 + 255) / 256, 256>>>(visible);
    gemm_kernel<<<dim3(SIMCOLS / 128, NPOS / 128), 256, 65536>>>(x, memory, sim);
    argmax_kernel<<<NPOS, 256>>>(sim, y, out_y);
    segsum_kernel<<<NPOS, 64>>>(x);
    update_kernel<<<MROWS, 32>>>(x, memory, params, out_mem);
}

// round 3
// speedup vs baseline: 1.8770x; 1.8770x over previous
#include <cuda_runtime.h>
#include <cuda_bf16.h>
#include <cstdint>
#include <cstddef>

#define NPOS 8192
#define NNEG 4096
#define DIM 64
#define MROWS 24576          // NPOS + 4*NNEG
#define XROWS 12288
#define SIMCOLS 24576
#define LRUC 1

#define BM 128
#define BN 256

typedef unsigned long long ull;
typedef uint32_t u32;

// ---------------- device scratch (no allocs allowed) ----------------
__device__ __align__(256) __nv_bfloat16 g_Abf[NPOS * 128];    // [row][Ah(64) | Al(64)]
__device__ __align__(256) __nv_bfloat16 g_Bbf[MROWS * 128];   // [row][Bh(64) | Bl(64)]
__device__ float g_get[NPOS * DIM];
__device__ float g_counts[NPOS];
__device__ float g_vis[NPOS];
__device__ int   g_yidx[NPOS];
__device__ ull   g_amax[NPOS];

// ---------------- PTX helpers ----------------
__device__ __forceinline__ u32 smem_u32(const void* p) {
    u32 a; asm("{ .reg .u64 t; cvta.to.shared.u64 t, %1; cvt.u32.u64 %0, t; }" : "=r"(a) : "l"(p));
    return a;
}
__device__ __forceinline__ void cpasync16(u32 dst, const void* src) {
    asm volatile("cp.async.cg.shared.global [%0], [%1], 16;" :: "r"(dst), "l"(src) : "memory");
}
#define CP_COMMIT()  asm volatile("cp.async.commit_group;" ::: "memory")
#define CP_WAIT(n)   asm volatile("cp.async.wait_group %0;" :: "n"(n) : "memory")

__device__ __forceinline__ void ldsm4(u32& r0, u32& r1, u32& r2, u32& r3, u32 addr) {
    asm volatile("ldmatrix.sync.aligned.m8n8.x4.shared.b16 {%0,%1,%2,%3}, [%4];"
                 : "=r"(r0), "=r"(r1), "=r"(r2), "=r"(r3) : "r"(addr));
}
__device__ __forceinline__ void mma16816(float& d0, float& d1, float& d2, float& d3,
                                         u32 a0, u32 a1, u32 a2, u32 a3, u32 b0, u32 b1) {
    asm volatile("mma.sync.aligned.m16n8k16.row.col.f32.bf16.bf16.f32 "
                 "{%0,%1,%2,%3}, {%4,%5,%6,%7}, {%8,%9}, {%0,%1,%2,%3};"
                 : "+f"(d0), "+f"(d1), "+f"(d2), "+f"(d3)
                 : "r"(a0), "r"(a1), "r"(a2), "r"(a3), "r"(b0), "r"(b1));
}
__device__ __forceinline__ u32 fkey(float v) {
    u32 u = __float_as_uint(v);
    return (u & 0x80000000u) ? ~u : (u | 0x80000000u);
}

// ---------------- split: fp32 -> (bf16 hi, bf16 lo) packed [row][128] ----------------
__global__ void split_kernel(const float* __restrict__ x, const float* __restrict__ mem) {
    const int nA = NPOS * DIM, nTot = nA + MROWS * DIM;
    for (int i = blockIdx.x * blockDim.x + threadIdx.x; i < nTot; i += gridDim.x * blockDim.x) {
        float v; __nv_bfloat16* base; int k;
        if (i < nA) { v = x[i];        base = g_Abf + (size_t)(i >> 6) * 128;        k = i & 63; }
        else { int j = i - nA; v = mem[j]; base = g_Bbf + (size_t)(j >> 6) * 128;    k = j & 63; }
        __nv_bfloat16 h = __float2bfloat16_rn(v);
        float r = v - __bfloat162float(h);
        base[k]      = h;
        base[64 + k] = __float2bfloat16_rn(r);
    }
}

// ---------------- zero scratch ----------------
__global__ void zero_kernel() {
    int i = blockIdx.x * blockDim.x + threadIdx.x;
    int stride = gridDim.x * blockDim.x;
    for (int j = i; j < NPOS * DIM; j += stride) g_get[j] = 0.0f;
    for (int j = i; j < NPOS; j += stride) { g_counts[j] = 0.0f; g_vis[j] = 0.0f; g_amax[j] = 0ull; }
}

__global__ void vis_kernel(const int* __restrict__ visible) {
    int i = blockIdx.x * blockDim.x + threadIdx.x;
    if (i < NPOS / 2) g_vis[visible[i]] = 1.0f;
}

// ---------------- bf16 split-GEMM via mma.sync + fused argmax partials ----------------
// C[8192,24576] = A*B^T with A=Ah+Al, B=Bh+Bl; sim = AhBh + AlBh + AhBl.
// CTA tile 128x256, warp tile 64x64, smem K = 128 (hi||lo) per operand row.
__global__ void __launch_bounds__(256, 1)
gemm_mma(const int* __restrict__ y, float* __restrict__ C) {
    extern __shared__ char smem[];
    const u32 sb = smem_u32(smem);
    const u32 As = sb;             // 128 rows * 256B = 32KB
    const u32 Bs = sb + 32768;     // 256 rows * 256B = 64KB
    int* ys = (int*)(smem + 98304);

    const int tid  = threadIdx.x;
    const int lane = tid & 31;
    const int w    = tid >> 5;
    const int wm   = w >> 2, wn = w & 3;
    const int m0   = blockIdx.y * BM;
    const int n0   = blockIdx.x * BN;
    const bool domax = (n0 < NPOS);

    // ---- cp.async staged loads: group0 = hi halves, group1 = lo halves ----
#pragma unroll
    for (int h = 0; h < 2; h++) {
#pragma unroll
        for (int i = 0; i < 4; i++) {           // A: 1024 chunks of 16B
            int idx = tid + i * 256;
            int r = idx >> 3, c = idx & 7;
            u32 dst = As + r * 256 + (u32)(((h * 8) | ((c ^ r) & 7)) * 16);
            cpasync16(dst, g_Abf + (size_t)(m0 + r) * 128 + h * 64 + c * 8);
        }
#pragma unroll
        for (int i = 0; i < 8; i++) {           // B: 2048 chunks of 16B
            int idx = tid + i * 256;
            int r = idx >> 3, c = idx & 7;
            u32 dst = Bs + r * 256 + (u32)(((h * 8) | ((c ^ r) & 7)) * 16);
            cpasync16(dst, g_Bbf + (size_t)(n0 + r) * 128 + h * 64 + c * 8);
        }
        CP_COMMIT();
    }
    if (domax && tid < BM) ys[tid] = y[m0 + tid];

    float acc[4][8][4];
#pragma unroll
    for (int mi = 0; mi < 4; mi++)
#pragma unroll
        for (int ni = 0; ni < 8; ni++)
#pragma unroll
            for (int q = 0; q < 4; q++) acc[mi][ni][q] = 0.0f;

    CP_WAIT(1);
    __syncthreads();

    const int wr = wm * 64, wc = wn * 64;

#pragma unroll
    for (int p = 0; p < 3; p++) {               // (Ah,Bh), (Al,Bh), (Ah,Bl)
        if (p == 1) { CP_WAIT(0); __syncthreads(); }
        const int ah = (p == 1) ? 8 : 0;
        const int bh = (p == 2) ? 8 : 0;
#pragma unroll
        for (int ks = 0; ks < 4; ks++) {
            u32 a[4][4];
#pragma unroll
            for (int mi = 0; mi < 4; mi++) {
                int row = wr + mi * 16 + (lane & 15);
                int ch  = ah + 2 * ks + (lane >> 4);
                u32 ad  = As + row * 256 + (u32)((((ch) & 8) | ((ch ^ row) & 7)) * 16);
                ldsm4(a[mi][0], a[mi][1], a[mi][2], a[mi][3], ad);
            }
            u32 b[4][4];
#pragma unroll
            for (int j = 0; j < 4; j++) {
                int n  = wc + j * 16 + (lane & 7) + ((lane >> 4) << 3);
                int ch = bh + 2 * ks + ((lane >> 3) & 1);
                u32 bd = Bs + n * 256 + (u32)(((ch & 8) | ((ch ^ n) & 7)) * 16);
                ldsm4(b[j][0], b[j][1], b[j][2], b[j][3], bd);
            }
#pragma unroll
            for (int mi = 0; mi < 4; mi++)
#pragma unroll
                for (int ni = 0; ni < 8; ni++) {
                    int j = ni >> 1, o = (ni & 1) * 2;
                    mma16816(acc[mi][ni][0], acc[mi][ni][1], acc[mi][ni][2], acc[mi][ni][3],
                             a[mi][0], a[mi][1], a[mi][2], a[mi][3], b[j][o], b[j][o + 1]);
                }
        }
    }

    // ---- epilogue: direct stores + fused per-row argmax partials ----
#pragma unroll
    for (int mi = 0; mi < 4; mi++) {
        int lr = wr + mi * 16 + (lane >> 2);
        float* p0 = C + (size_t)(m0 + lr) * SIMCOLS + n0 + wc + (lane & 3) * 2;
        float* p1 = p0 + (size_t)8 * SIMCOLS;
        ull k0 = 0, k1 = 0;
        int yv0 = -1, yv1 = -1;
        if (domax) { yv0 = ys[lr]; yv1 = ys[lr + 8]; }
#pragma unroll
        for (int ni = 0; ni < 8; ni++) {
            float c0 = acc[mi][ni][0], c1 = acc[mi][ni][1];
            float c2 = acc[mi][ni][2], c3 = acc[mi][ni][3];
            *(float2*)(p0 + ni * 8) = make_float2(c0, c1);
            *(float2*)(p1 + ni * 8) = make_float2(c2, c3);
            if (domax) {
                int col = n0 + wc + ni * 8 + (lane & 3) * 2;
                float v0 = c0 + (col     == yv0 ? 2.0f : 0.0f);
                float v1 = c1 + (col + 1 == yv0 ? 2.0f : 0.0f);
                float v2 = c2 + (col     == yv1 ? 2.0f : 0.0f);
                float v3 = c3 + (col + 1 == yv1 ? 2.0f : 0.0f);
                ull q;
                q = ((ull)fkey(v0) << 32) | (u32)(0xFFFFFFFFu - (u32)col);       if (q > k0) k0 = q;
                q = ((ull)fkey(v1) << 32) | (u32)(0xFFFFFFFFu - (u32)(col + 1)); if (q > k0) k0 = q;
                q = ((ull)fkey(v2) << 32) | (u32)(0xFFFFFFFFu - (u32)col);       if (q > k1) k1 = q;
                q = ((ull)fkey(v3) << 32) | (u32)(0xFFFFFFFFu - (u32)(col + 1)); if (q > k1) k1 = q;
            }
        }
        if (domax) {
#pragma unroll
            for (int o2 = 1; o2 <= 2; o2 <<= 1) {
                ull t0 = __shfl_xor_sync(0xffffffffu, k0, o2); if (t0 > k0) k0 = t0;
                ull t1 = __shfl_xor_sync(0xffffffffu, k1, o2); if (t1 > k1) k1 = t1;
            }
            if ((lane & 3) == 0) {
                atomicMax(&g_amax[m0 + lr], k0);
                atomicMax(&g_amax[m0 + lr + 8], k1);
            }
        }
    }
}

// ---------------- finalize argmax ----------------
__global__ void finalize_kernel(float* __restrict__ out_y) {
    int r = blockIdx.x * blockDim.x + threadIdx.x;
    if (r < NPOS) {
        ull k = g_amax[r];
        int idx = (int)(0xFFFFFFFFu - (u32)(k & 0xFFFFFFFFull));
        g_yidx[r] = idx;
        out_y[r] = (float)idx;
    }
}

// ---------------- segment sums ----------------
__global__ void segsum_kernel(const float* __restrict__ x) {
    int i = blockIdx.x;
    int t = threadIdx.x;
    int idx = g_yidx[i];
    atomicAdd(&g_get[idx * DIM + t], x[(size_t)i * DIM + t]);
    if (t == 0) atomicAdd(&g_counts[idx], 1.0f);
}

// ---------------- memory update + normalize + slot writes ----------------
__global__ void update_kernel(const float* __restrict__ x, const float* __restrict__ memory,
                              const float* __restrict__ params, float* __restrict__ outm) {
    int r = blockIdx.x;
    int t = threadIdx.x;
    if (r < NPOS) {
        float mom   = params[3];
        float cnt   = g_counts[r];
        float valid = (cnt > 0.1f ? 1.0f : 0.0f) * g_vis[r];
        float msc   = valid * mom + 1.0f - valid;
        float gsc   = (1.0f - mom) * valid;
        float denom = cnt + 1e-8f;
        float v0 = memory[(size_t)r * DIM + t]      * msc + (g_get[r * DIM + t]      / denom) * gsc;
        float v1 = memory[(size_t)r * DIM + t + 32] * msc + (g_get[r * DIM + t + 32] / denom) * gsc;
        float ss = v0 * v0 + v1 * v1;
#pragma unroll
        for (int o = 16; o; o >>= 1) ss += __shfl_xor_sync(0xffffffffu, ss, o);
        float inv = 1.0f / fmaxf(sqrtf(ss), 1e-12f);
        outm[(size_t)r * DIM + t]      = v0 * inv;
        outm[(size_t)r * DIM + t + 32] = v1 * inv;
    } else if (r >= NPOS + LRUC * NNEG && r < NPOS + LRUC * NNEG + NNEG) {
        int xs = NPOS + (r - (NPOS + LRUC * NNEG));
        outm[(size_t)r * DIM + t]      = x[(size_t)xs * DIM + t];
        outm[(size_t)r * DIM + t + 32] = x[(size_t)xs * DIM + t + 32];
    } else {
        outm[(size_t)r * DIM + t]      = memory[(size_t)r * DIM + t];
        outm[(size_t)r * DIM + t + 32] = memory[(size_t)r * DIM + t + 32];
    }
}

// ---------------- launch ----------------
extern "C" void kernel_launch(void* const* d_in, const int* in_sizes, int n_in,
                              void* d_out, int out_size) {
    const float* x = nullptr;
    const int*   y = nullptr;
    const int*   visible = nullptr;
    const float* memory = nullptr;
    const float* params = nullptr;
    for (int i = 0; i < n_in; i++) {
        switch (in_sizes[i]) {
            case XROWS * DIM: x = (const float*)d_in[i]; break;
            case NPOS:        y = (const int*)d_in[i]; break;
            case NPOS / 2:    visible = (const int*)d_in[i]; break;
            case MROWS * DIM: memory = (const float*)d_in[i]; break;
            case 4:           params = (const float*)d_in[i]; break;
            default: break;
        }
    }

    float* sim     = (float*)d_out;
    float* out_y   = sim + (size_t)NPOS * SIMCOLS;
    float* out_mem = out_y + NPOS;

    const int SMEM_TOTAL = 98304 + 512;   // A(32K) + B(64K) + y tile
    cudaFuncSetAttribute(gemm_mma, cudaFuncAttributeMaxDynamicSharedMemorySize, SMEM_TOTAL);

    split_kernel<<<2048, 256>>>(x, memory);
    zero_kernel<<<512, 256>>>();
    vis_kernel<<<(NPOS / 2 + 255) / 256, 256>>>(visible);
    gemm_mma<<<dim3(SIMCOLS / BN, NPOS / BM), 256, SMEM_TOTAL>>>(y, sim);
    finalize_kernel<<<(NPOS + 255) / 256, 256>>>(out_y);
    segsum_kernel<<<NPOS, 64>>>(x);
    update_kernel<<<MROWS, 32>>>(x, memory, params, out_mem);
}

// round 4
// speedup vs baseline: 2.1952x; 1.1695x over previous
#include <cuda_runtime.h>
#include <cuda_bf16.h>
#include <cstdint>
#include <cstddef>

#define NPOS 8192
#define NNEG 4096
#define DIM 64
#define MROWS 24576          // NPOS + 4*NNEG
#define XROWS 12288
#define SIMCOLS 24576
#define LRUC 1

#define BM 128
#define BN 128

typedef unsigned long long ull;
typedef uint32_t u32;

// ---------------- device scratch (no allocs allowed) ----------------
__device__ __align__(256) __nv_bfloat16 g_Abf[NPOS * 128];    // [row][Ah(64) | Al(64)]
__device__ __align__(256) __nv_bfloat16 g_Bbf[MROWS * 128];   // [row][Bh(64) | Bl(64)]
__device__ float g_get[NPOS * DIM];
__device__ float g_counts[NPOS];
__device__ float g_vis[NPOS];
__device__ int   g_yidx[NPOS];
__device__ ull   g_amax[NPOS];

// ---------------- PTX helpers ----------------
__device__ __forceinline__ u32 smem_u32(const void* p) {
    u32 a; asm("{ .reg .u64 t; cvta.to.shared.u64 t, %1; cvt.u32.u64 %0, t; }" : "=r"(a) : "l"(p));
    return a;
}
__device__ __forceinline__ void cpasync16(u32 dst, const void* src) {
    asm volatile("cp.async.cg.shared.global [%0], [%1], 16;" :: "r"(dst), "l"(src) : "memory");
}
#define CP_COMMIT()  asm volatile("cp.async.commit_group;" ::: "memory")
#define CP_WAIT(n)   asm volatile("cp.async.wait_group %0;" :: "n"(n) : "memory")

__device__ __forceinline__ void ldsm4(u32& r0, u32& r1, u32& r2, u32& r3, u32 addr) {
    asm volatile("ldmatrix.sync.aligned.m8n8.x4.shared.b16 {%0,%1,%2,%3}, [%4];"
                 : "=r"(r0), "=r"(r1), "=r"(r2), "=r"(r3) : "r"(addr));
}
__device__ __forceinline__ void mma16816(float& d0, float& d1, float& d2, float& d3,
                                         u32 a0, u32 a1, u32 a2, u32 a3, u32 b0, u32 b1) {
    asm volatile("mma.sync.aligned.m16n8k16.row.col.f32.bf16.bf16.f32 "
                 "{%0,%1,%2,%3}, {%4,%5,%6,%7}, {%8,%9}, {%0,%1,%2,%3};"
                 : "+f"(d0), "+f"(d1), "+f"(d2), "+f"(d3)
                 : "r"(a0), "r"(a1), "r"(a2), "r"(a3), "r"(b0), "r"(b1));
}
__device__ __forceinline__ u32 fkey(float v) {
    u32 u = __float_as_uint(v);
    return (u & 0x80000000u) ? ~u : (u | 0x80000000u);
}

// ---------------- split: fp32 -> (bf16 hi, bf16 lo) packed [row][128] ----------------
__global__ void split_kernel(const float* __restrict__ x, const float* __restrict__ mem) {
    const int nA = NPOS * DIM, nTot = nA + MROWS * DIM;
    for (int i = blockIdx.x * blockDim.x + threadIdx.x; i < nTot; i += gridDim.x * blockDim.x) {
        float v; __nv_bfloat16* base; int k;
        if (i < nA) { v = x[i];        base = g_Abf + (size_t)(i >> 6) * 128;        k = i & 63; }
        else { int j = i - nA; v = mem[j]; base = g_Bbf + (size_t)(j >> 6) * 128;    k = j & 63; }
        __nv_bfloat16 h = __float2bfloat16_rn(v);
        float r = v - __bfloat162float(h);
        base[k]      = h;
        base[64 + k] = __float2bfloat16_rn(r);
    }
}

// ---------------- zero scratch ----------------
__global__ void zero_kernel() {
    int i = blockIdx.x * blockDim.x + threadIdx.x;
    int stride = gridDim.x * blockDim.x;
    for (int j = i; j < NPOS * DIM; j += stride) g_get[j] = 0.0f;
    for (int j = i; j < NPOS; j += stride) { g_counts[j] = 0.0f; g_vis[j] = 0.0f; g_amax[j] = 0ull; }
}

__global__ void vis_kernel(const int* __restrict__ visible) {
    int i = blockIdx.x * blockDim.x + threadIdx.x;
    if (i < NPOS / 2) g_vis[visible[i]] = 1.0f;
}

// ---------------- bf16 split-GEMM via mma.sync + fused argmax partials ----------------
// C[8192,24576] = A*B^T with A=Ah+Al, B=Bh+Bl; sim = AhBh + AlBh + AhBl.
// CTA tile 128x128, warp tile 64x32 (2x4 warps), 2 CTAs/SM for latency hiding.
__global__ void __launch_bounds__(256, 2)
gemm_mma(const int* __restrict__ y, float* __restrict__ C) {
    extern __shared__ char smem[];
    const u32 sb = smem_u32(smem);
    const u32 As = sb;             // 128 rows * 256B = 32KB
    const u32 Bs = sb + 32768;     // 128 rows * 256B = 32KB
    int* ys = (int*)(smem + 65536);

    const int tid  = threadIdx.x;
    const int lane = tid & 31;
    const int w    = tid >> 5;
    const int wm   = w >> 2, wn = w & 3;
    const int m0   = blockIdx.y * BM;
    const int n0   = blockIdx.x * BN;
    const bool domax = (n0 < NPOS);

    // ---- cp.async staged loads: group0 = hi halves, group1 = lo halves ----
#pragma unroll
    for (int h = 0; h < 2; h++) {
#pragma unroll
        for (int i = 0; i < 4; i++) {           // A: 1024 chunks of 16B
            int idx = tid + i * 256;
            int r = idx >> 3, c = idx & 7;
            u32 dst = As + r * 256 + (u32)(((h * 8) | ((c ^ r) & 7)) * 16);
            cpasync16(dst, g_Abf + (size_t)(m0 + r) * 128 + h * 64 + c * 8);
        }
#pragma unroll
        for (int i = 0; i < 4; i++) {           // B: 1024 chunks of 16B
            int idx = tid + i * 256;
            int r = idx >> 3, c = idx & 7;
            u32 dst = Bs + r * 256 + (u32)(((h * 8) | ((c ^ r) & 7)) * 16);
            cpasync16(dst, g_Bbf + (size_t)(n0 + r) * 128 + h * 64 + c * 8);
        }
        CP_COMMIT();
    }
    if (domax && tid < BM) ys[tid] = y[m0 + tid];

    float acc[4][4][4];
#pragma unroll
    for (int mi = 0; mi < 4; mi++)
#pragma unroll
        for (int ni = 0; ni < 4; ni++)
#pragma unroll
            for (int q = 0; q < 4; q++) acc[mi][ni][q] = 0.0f;

    CP_WAIT(1);
    __syncthreads();

    const int wr = wm * 64, wc = wn * 32;

#pragma unroll
    for (int p = 0; p < 3; p++) {               // (Ah,Bh), (Al,Bh), (Ah,Bl)
        if (p == 1) { CP_WAIT(0); __syncthreads(); }
        const int ah = (p == 1) ? 8 : 0;
        const int bh = (p == 2) ? 8 : 0;
#pragma unroll
        for (int ks = 0; ks < 4; ks++) {
            u32 a[4][4];
#pragma unroll
            for (int mi = 0; mi < 4; mi++) {
                int row = wr + mi * 16 + (lane & 15);
                int ch  = ah + 2 * ks + (lane >> 4);
                u32 ad  = As + row * 256 + (u32)((((ch) & 8) | ((ch ^ row) & 7)) * 16);
                ldsm4(a[mi][0], a[mi][1], a[mi][2], a[mi][3], ad);
            }
            u32 b[2][4];
#pragma unroll
            for (int j = 0; j < 2; j++) {
                int n  = wc + j * 16 + (lane & 7) + ((lane >> 4) << 3);
                int ch = bh + 2 * ks + ((lane >> 3) & 1);
                u32 bd = Bs + n * 256 + (u32)(((ch & 8) | ((ch ^ n) & 7)) * 16);
                ldsm4(b[j][0], b[j][1], b[j][2], b[j][3], bd);
            }
#pragma unroll
            for (int mi = 0; mi < 4; mi++)
#pragma unroll
                for (int ni = 0; ni < 4; ni++) {
                    int j = ni >> 1, o = (ni & 1) * 2;
                    mma16816(acc[mi][ni][0], acc[mi][ni][1], acc[mi][ni][2], acc[mi][ni][3],
                             a[mi][0], a[mi][1], a[mi][2], a[mi][3], b[j][o], b[j][o + 1]);
                }
        }
    }

    // ---- epilogue: direct stores + fused per-row argmax partials ----
#pragma unroll
    for (int mi = 0; mi < 4; mi++) {
        int lr = wr + mi * 16 + (lane >> 2);
        float* p0 = C + (size_t)(m0 + lr) * SIMCOLS + n0 + wc + (lane & 3) * 2;
        float* p1 = p0 + (size_t)8 * SIMCOLS;
        ull k0 = 0, k1 = 0;
        int yv0 = -1, yv1 = -1;
        if (domax) { yv0 = ys[lr]; yv1 = ys[lr + 8]; }
#pragma unroll
        for (int ni = 0; ni < 4; ni++) {
            float c0 = acc[mi][ni][0], c1 = acc[mi][ni][1];
            float c2 = acc[mi][ni][2], c3 = acc[mi][ni][3];
            *(float2*)(p0 + ni * 8) = make_float2(c0, c1);
            *(float2*)(p1 + ni * 8) = make_float2(c2, c3);
            if (domax) {
                int col = n0 + wc + ni * 8 + (lane & 3) * 2;
                float v0 = c0 + (col     == yv0 ? 2.0f : 0.0f);
                float v1 = c1 + (col + 1 == yv0 ? 2.0f : 0.0f);
                float v2 = c2 + (col     == yv1 ? 2.0f : 0.0f);
                float v3 = c3 + (col + 1 == yv1 ? 2.0f : 0.0f);
                ull q;
                q = ((ull)fkey(v0) << 32) | (u32)(0xFFFFFFFFu - (u32)col);       if (q > k0) k0 = q;
                q = ((ull)fkey(v1) << 32) | (u32)(0xFFFFFFFFu - (u32)(col + 1)); if (q > k0) k0 = q;
                q = ((ull)fkey(v2) << 32) | (u32)(0xFFFFFFFFu - (u32)col);       if (q > k1) k1 = q;
                q = ((ull)fkey(v3) << 32) | (u32)(0xFFFFFFFFu - (u32)(col + 1)); if (q > k1) k1 = q;
            }
        }
        if (domax) {
#pragma unroll
            for (int o2 = 1; o2 <= 2; o2 <<= 1) {
                ull t0 = __shfl_xor_sync(0xffffffffu, k0, o2); if (t0 > k0) k0 = t0;
                ull t1 = __shfl_xor_sync(0xffffffffu, k1, o2); if (t1 > k1) k1 = t1;
            }
            if ((lane & 3) == 0) {
                atomicMax(&g_amax[m0 + lr], k0);
                atomicMax(&g_amax[m0 + lr + 8], k1);
            }
        }
    }
}

// ---------------- finalize argmax ----------------
__global__ void finalize_kernel(float* __restrict__ out_y) {
    int r = blockIdx.x * blockDim.x + threadIdx.x;
    if (r < NPOS) {
        ull k = g_amax[r];
        int idx = (int)(0xFFFFFFFFu - (u32)(k & 0xFFFFFFFFull));
        g_yidx[r] = idx;
        out_y[r] = (float)idx;
    }
}

// ---------------- segment sums ----------------
__global__ void segsum_kernel(const float* __restrict__ x) {
    int i = blockIdx.x;
    int t = threadIdx.x;
    int idx = g_yidx[i];
    atomicAdd(&g_get[idx * DIM + t], x[(size_t)i * DIM + t]);
    if (t == 0) atomicAdd(&g_counts[idx], 1.0f);
}

// ---------------- memory update + normalize + slot writes ----------------
__global__ void update_kernel(const float* __restrict__ x, const float* __restrict__ memory,
                              const float* __restrict__ params, float* __restrict__ outm) {
    int r = blockIdx.x;
    int t = threadIdx.x;
    if (r < NPOS) {
        float mom   = params[3];
        float cnt   = g_counts[r];
        float valid = (cnt > 0.1f ? 1.0f : 0.0f) * g_vis[r];
        float msc   = valid * mom + 1.0f - valid;
        float gsc   = (1.0f - mom) * valid;
        float denom = cnt + 1e-8f;
        float v0 = memory[(size_t)r * DIM + t]      * msc + (g_get[r * DIM + t]      / denom) * gsc;
        float v1 = memory[(size_t)r * DIM + t + 32] * msc + (g_get[r * DIM + t + 32] / denom) * gsc;
        float ss = v0 * v0 + v1 * v1;
#pragma unroll
        for (int o = 16; o; o >>= 1) ss += __shfl_xor_sync(0xffffffffu, ss, o);
        float inv = 1.0f / fmaxf(sqrtf(ss), 1e-12f);
        outm[(size_t)r * DIM + t]      = v0 * inv;
        outm[(size_t)r * DIM + t + 32] = v1 * inv;
    } else if (r >= NPOS + LRUC * NNEG && r < NPOS + LRUC * NNEG + NNEG) {
        int xs = NPOS + (r - (NPOS + LRUC * NNEG));
        outm[(size_t)r * DIM + t]      = x[(size_t)xs * DIM + t];
        outm[(size_t)r * DIM + t + 32] = x[(size_t)xs * DIM + t + 32];
    } else {
        outm[(size_t)r * DIM + t]      = memory[(size_t)r * DIM + t];
        outm[(size_t)r * DIM + t + 32] = memory[(size_t)r * DIM + t + 32];
    }
}

// ---------------- launch ----------------
extern "C" void kernel_launch(void* const* d_in, const int* in_sizes, int n_in,
                              void* d_out, int out_size) {
    const float* x = nullptr;
    const int*   y = nullptr;
    const int*   visible = nullptr;
    const float* memory = nullptr;
    const float* params = nullptr;
    for (int i = 0; i < n_in; i++) {
        switch (in_sizes[i]) {
            case XROWS * DIM: x = (const float*)d_in[i]; break;
            case NPOS:        y = (const int*)d_in[i]; break;
            case NPOS / 2:    visible = (const int*)d_in[i]; break;
            case MROWS * DIM: memory = (const float*)d_in[i]; break;
            case 4:           params = (const float*)d_in[i]; break;
            default: break;
        }
    }

    float* sim     = (float*)d_out;
    float* out_y   = sim + (size_t)NPOS * SIMCOLS;
    float* out_mem = out_y + NPOS;

    const int SMEM_TOTAL = 65536 + 512;   // A(32K) + B(32K) + y tile
    cudaFuncSetAttribute(gemm_mma, cudaFuncAttributeMaxDynamicSharedMemorySize, SMEM_TOTAL);

    split_kernel<<<2048, 256>>>(x, memory);
    zero_kernel<<<512, 256>>>();
    vis_kernel<<<(NPOS / 2 + 255) / 256, 256>>>(visible);
    gemm_mma<<<dim3(SIMCOLS / BN, NPOS / BM), 256, SMEM_TOTAL>>>(y, sim);
    finalize_kernel<<<(NPOS + 255) / 256, 256>>>(out_y);
    segsum_kernel<<<NPOS, 64>>>(x);
    update_kernel<<<MROWS, 32>>>(x, memory, params, out_mem);
}